// round 4
// baseline (speedup 1.0000x reference)
#include <cuda_runtime.h>
#include <cuda_bf16.h>
#include <math.h>

// Problem constants
#define Bc   2
#define Tc   2048
#define Dc   1024
#define Hc   16
#define Kc   64
#define Vc   64
#define Wc   256
#define BANKc 64
#define CUEc 50250
#define NTOK (Bc*Tc)            // 4096
#define NELEM (Bc*Tc*Dc)        // 4,194,304

// ---------------- scratch buffers (static device memory) ----------------
__device__ float g_xn[NELEM];
__device__ float g_q[NELEM];
__device__ float g_k[NELEM];
__device__ float g_v[NELEM];
__device__ float g_attn[NELEM];
__device__ float g_localp[NELEM];
__device__ float g_qg[NELEM];
__device__ float g_retr[NELEM];
__device__ float g_retout[NELEM];
__device__ float g_gmean[NTOK];

// ---------------- helpers ----------------
__device__ __forceinline__ float warpSum(float v) {
    #pragma unroll
    for (int o = 16; o; o >>= 1) v += __shfl_xor_sync(0xffffffffu, v, o);
    return v;
}
__device__ __forceinline__ float warpMax(float v) {
    #pragma unroll
    for (int o = 16; o; o >>= 1) v = fmaxf(v, __shfl_xor_sync(0xffffffffu, v, o));
    return v;
}

// ---------------- RMSNorm ----------------
__global__ __launch_bounds__(256) void rmsnorm_kernel(
    const float* __restrict__ x, const float* __restrict__ w, float* __restrict__ xn)
{
    int n = blockIdx.x;
    const float* xp = x + (size_t)n * Dc;
    float s = 0.f;
    for (int d = threadIdx.x; d < Dc; d += 256) { float v = xp[d]; s += v * v; }
    __shared__ float red[8];
    s = warpSum(s);
    int warp = threadIdx.x >> 5, lane = threadIdx.x & 31;
    if (lane == 0) red[warp] = s;
    __syncthreads();
    if (warp == 0) {
        float t = lane < 8 ? red[lane] : 0.f;
        t = warpSum(t);
        if (lane == 0) red[0] = rsqrtf(t / (float)Dc + 1e-6f);
    }
    __syncthreads();
    float inv = red[0];
    float* op = xn + (size_t)n * Dc;
    for (int d = threadIdx.x; d < Dc; d += 256) op[d] = xp[d] * inv * w[d];
}

// ---------------- GEMM: C[M,N] = A[M,Kd] @ W[N,Kd]^T ----------------
#define GBM 64
#define GBN 64
#define GBK 16
__global__ __launch_bounds__(256) void gemm_awt(
    const float* __restrict__ A, const float* __restrict__ W,
    float* __restrict__ C, int M, int N, int Kd)
{
    __shared__ float As[GBK][GBM + 1];
    __shared__ float Ws[GBK][GBN + 1];
    int tid = threadIdx.x;
    int bm = blockIdx.y * GBM;
    int bn = blockIdx.x * GBN;
    int tx = tid & 15, ty = tid >> 4;
    float acc[4][4] = {};
    int lr  = tid >> 2;          // 0..63 row within tile
    int lc4 = (tid & 3) * 4;     // 0,4,8,12 col offset
    for (int k0 = 0; k0 < Kd; k0 += GBK) {
        float4 av = *(const float4*)(A + (size_t)(bm + lr) * Kd + k0 + lc4);
        float4 wv = *(const float4*)(W + (size_t)(bn + lr) * Kd + k0 + lc4);
        As[lc4 + 0][lr] = av.x; As[lc4 + 1][lr] = av.y;
        As[lc4 + 2][lr] = av.z; As[lc4 + 3][lr] = av.w;
        Ws[lc4 + 0][lr] = wv.x; Ws[lc4 + 1][lr] = wv.y;
        Ws[lc4 + 2][lr] = wv.z; Ws[lc4 + 3][lr] = wv.w;
        __syncthreads();
        #pragma unroll
        for (int kk = 0; kk < GBK; kk++) {
            float a[4], b[4];
            #pragma unroll
            for (int i = 0; i < 4; i++) a[i] = As[kk][ty * 4 + i];
            #pragma unroll
            for (int j = 0; j < 4; j++) b[j] = Ws[kk][tx * 4 + j];
            #pragma unroll
            for (int i = 0; i < 4; i++)
                #pragma unroll
                for (int j = 0; j < 4; j++)
                    acc[i][j] = fmaf(a[i], b[j], acc[i][j]);
        }
        __syncthreads();
    }
    #pragma unroll
    for (int i = 0; i < 4; i++) {
        float* cp = C + (size_t)(bm + ty * 4 + i) * N + bn + tx * 4;
        #pragma unroll
        for (int j = 0; j < 4; j++) cp[j] = acc[i][j];
    }
}

// ---------------- RoPE (in-place on q and k), 8 warps/block ----------------
__global__ __launch_bounds__(256) void rope_kernel(float* __restrict__ q, float* __restrict__ k)
{
    int warp = threadIdx.x >> 5;
    int j = threadIdx.x & 31;             // 0..31
    int bth = blockIdx.x * 8 + warp;      // enumerates (b,t,h) in memory order
    int t = (bth / Hc) % Tc;
    float inv = powf(10000.0f, -(float)j / 32.0f);
    float ang = (float)t * inv;
    float c, s;
    sincosf(ang, &s, &c);                 // accurate version: ang can be ~2000 rad
    float* qp = q + (size_t)bth * Kc;
    float* kp = k + (size_t)bth * Kc;
    float q1 = qp[j], q2 = qp[j + 32];
    qp[j]      = q1 * c - q2 * s;
    qp[j + 32] = q2 * c + q1 * s;
    float k1 = kp[j], k2 = kp[j + 32];
    kp[j]      = k1 * c - k2 * s;
    kp[j + 32] = k2 * c + k1 * s;
}

// ---------------- Sliding-window attention: warp per (b,h,t) ----------------
__global__ __launch_bounds__(128) void attn_kernel(
    const float* __restrict__ q, const float* __restrict__ k,
    const float* __restrict__ v, float* __restrict__ out)
{
    __shared__ float qsh[4][Kc];
    __shared__ float ssh[4][Wc + 1];
    int warp = threadIdx.x >> 5, lane = threadIdx.x & 31;
    int gidx = blockIdx.x * 4 + warp;       // ((b*H + h)*T + t)
    int t = gidx % Tc;
    int bh = gidx / Tc;
    int h = bh % Hc;
    int b = bh / Hc;

    const float* qp = q + ((size_t)(b * Tc + t) * Hc + h) * Kc;
    qsh[warp][lane]      = qp[lane];
    qsh[warp][lane + 32] = qp[lane + 32];
    __syncwarp();

    int s_start = t - Wc; if (s_start < 0) s_start = 0;
    int S = t - s_start + 1;                // <= 257

    float mloc = -1e30f;
    for (int idx = lane; idx < S; idx += 32) {
        int s = s_start + idx;
        const float4* kp4 = (const float4*)(k + ((size_t)(b * Tc + s) * Hc + h) * Kc);
        float d = 0.f;
        #pragma unroll
        for (int kk = 0; kk < 16; kk++) {
            float4 kv = kp4[kk];
            d = fmaf(qsh[warp][4 * kk + 0], kv.x, d);
            d = fmaf(qsh[warp][4 * kk + 1], kv.y, d);
            d = fmaf(qsh[warp][4 * kk + 2], kv.z, d);
            d = fmaf(qsh[warp][4 * kk + 3], kv.w, d);
        }
        d *= 0.125f;                        // K^-0.5
        ssh[warp][idx] = d;
        mloc = fmaxf(mloc, d);
    }
    float mx = warpMax(mloc);
    __syncwarp();
    float sl = 0.f;
    for (int idx = lane; idx < S; idx += 32) {
        float e = __expf(ssh[warp][idx] - mx);
        ssh[warp][idx] = e;
        sl += e;
    }
    float ssum = warpSum(sl);
    float invs = 1.0f / ssum;
    __syncwarp();

    int d0 = lane * 2;
    float o0 = 0.f, o1 = 0.f;
    for (int idx = 0; idx < S; idx++) {
        float p = ssh[warp][idx];
        const float2* vp = (const float2*)(v + ((size_t)(b * Tc + s_start + idx) * Hc + h) * Kc);
        float2 v2 = vp[lane];
        o0 = fmaf(p, v2.x, o0);
        o1 = fmaf(p, v2.y, o1);
    }
    float* op = out + ((size_t)(b * Tc + t) * Hc + h) * Vc;
    op[d0]     = o0 * invs;
    op[d0 + 1] = o1 * invs;
}

// ---------------- gather-replace q_g from key_bank ----------------
__global__ __launch_bounds__(256) void gather_kernel(
    const int* __restrict__ input_ids, const float* __restrict__ key_bank,
    float* __restrict__ qg)
{
    int n = blockIdx.x;
    int idx = input_ids[n] - CUEc;
    if (idx < 0 || idx >= BANKc) return;
    for (int i = threadIdx.x; i < Hc * Kc; i += 256) {
        int h = i >> 6, kk = i & 63;
        qg[(size_t)n * (Hc * Kc) + i] = key_bank[((size_t)h * BANKc + idx) * Kc + kk];
    }
}

// ---------------- retrieval: retrieved[b,t,h,v] = sum_k state[b,h,k,v]*qg[b,t,h,k] ----
__global__ __launch_bounds__(256) void retrieve_kernel(
    const float* __restrict__ state, const float* __restrict__ qg, float* __restrict__ out)
{
    __shared__ float st[Kc * Vc];           // 16 KB
    __shared__ float qsh[8][Kc];
    int bh = blockIdx.x;                    // b*H + h
    int b = bh / Hc, h = bh % Hc;
    const float* sp = state + (size_t)bh * Kc * Vc;
    for (int i = threadIdx.x; i < Kc * Vc; i += 256) st[i] = sp[i];
    int warp = threadIdx.x >> 5, lane = threadIdx.x & 31;
    int t = blockIdx.y * 8 + warp;
    const float* qp = qg + ((size_t)(b * Tc + t) * Hc + h) * Kc;
    qsh[warp][lane]      = qp[lane];
    qsh[warp][lane + 32] = qp[lane + 32];
    __syncthreads();
    float o0 = 0.f, o1 = 0.f;
    #pragma unroll
    for (int kk = 0; kk < Kc; kk++) {
        float qv = qsh[warp][kk];
        float2 s2 = ((const float2*)(st + kk * Vc))[lane];
        o0 = fmaf(qv, s2.x, o0);
        o1 = fmaf(qv, s2.y, o1);
    }
    float* op = out + ((size_t)(b * Tc + t) * Hc + h) * Vc;
    op[lane * 2]     = o0;
    op[lane * 2 + 1] = o1;
}

// ---------------- gate mean: sigmoid(xn @ w_gate^T + b_gate), mean over H ----------
__global__ __launch_bounds__(512) void gate_kernel(
    const float* __restrict__ xn, const float* __restrict__ w_gate,
    const float* __restrict__ b_gate, float* __restrict__ gmean)
{
    __shared__ float gsh[Hc];
    int n = blockIdx.x;
    int warp = threadIdx.x >> 5, lane = threadIdx.x & 31;   // warp == head
    const float* xp = xn + (size_t)n * Dc;
    const float* wp = w_gate + (size_t)warp * Dc;
    float s = 0.f;
    for (int d = lane; d < Dc; d += 32) s = fmaf(xp[d], wp[d], s);
    s = warpSum(s);
    if (lane == 0) gsh[warp] = 1.0f / (1.0f + __expf(-(s + b_gate[warp])));
    __syncthreads();
    if (threadIdx.x == 0) {
        float acc = 0.f;
        #pragma unroll
        for (int h = 0; h < Hc; h++) acc += gsh[h];
        gmean[n] = acc / (float)Hc;
    }
}

// ---------------- final combine ----------------
__global__ __launch_bounds__(256) void combine_kernel(
    const float* __restrict__ x, const float* __restrict__ localp,
    const float* __restrict__ retout, const float* __restrict__ gmean,
    float* __restrict__ out)
{
    int i = blockIdx.x * 256 + threadIdx.x;
    int n = i >> 10;                        // i / D
    out[i] = x[i] + 0.3f * localp[i] + gmean[n] * retout[i];
}

// ---------------- launch ----------------
extern "C" void kernel_launch(void* const* d_in, const int* in_sizes, int n_in,
                              void* d_out, int out_size)
{
    const float* x         = (const float*)d_in[0];
    const float* gdn_state = (const float*)d_in[1];
    const int*   input_ids = (const int*)  d_in[2];
    const float* key_bank  = (const float*)d_in[3];
    const float* norm_w    = (const float*)d_in[4];
    const float* wq        = (const float*)d_in[5];
    const float* wk        = (const float*)d_in[6];
    const float* wv        = (const float*)d_in[7];
    const float* wo        = (const float*)d_in[8];
    const float* w_gq      = (const float*)d_in[9];
    const float* w_ro      = (const float*)d_in[10];
    const float* w_gate    = (const float*)d_in[11];
    const float* b_gate    = (const float*)d_in[12];
    float* out = (float*)d_out;

    float *xn, *q, *k, *v, *attn, *localp, *qg, *retr, *retout, *gmean;
    cudaGetSymbolAddress((void**)&xn,     g_xn);
    cudaGetSymbolAddress((void**)&q,      g_q);
    cudaGetSymbolAddress((void**)&k,      g_k);
    cudaGetSymbolAddress((void**)&v,      g_v);
    cudaGetSymbolAddress((void**)&attn,   g_attn);
    cudaGetSymbolAddress((void**)&localp, g_localp);
    cudaGetSymbolAddress((void**)&qg,     g_qg);
    cudaGetSymbolAddress((void**)&retr,   g_retr);
    cudaGetSymbolAddress((void**)&retout, g_retout);
    cudaGetSymbolAddress((void**)&gmean,  g_gmean);

    // 1. RMSNorm
    rmsnorm_kernel<<<NTOK, 256>>>(x, norm_w, xn);

    dim3 ggrid(Dc / GBN, NTOK / GBM);   // (16, 64)
    // 2. projections
    gemm_awt<<<ggrid, 256>>>(xn, wq,   q,  NTOK, Dc, Dc);
    gemm_awt<<<ggrid, 256>>>(xn, wk,   k,  NTOK, Dc, Dc);
    gemm_awt<<<ggrid, 256>>>(xn, wv,   v,  NTOK, Dc, Dc);
    gemm_awt<<<ggrid, 256>>>(xn, w_gq, qg, NTOK, Dc, Dc);

    // 3. RoPE on q,k
    rope_kernel<<<Bc * Tc * Hc / 8, 256>>>(q, k);

    // 4. attention
    attn_kernel<<<Bc * Hc * Tc / 4, 128>>>(q, k, v, attn);

    // 5. local output projection
    gemm_awt<<<ggrid, 256>>>(attn, wo, localp, NTOK, Dc, Dc);

    // 6. gather-replace q_g
    gather_kernel<<<NTOK, 256>>>(input_ids, key_bank, qg);

    // 7. retrieval einsum
    {
        dim3 rg(Bc * Hc, Tc / 8);
        retrieve_kernel<<<rg, 256>>>(gdn_state, qg, retr);
    }

    // 8. retrieval output projection
    gemm_awt<<<ggrid, 256>>>(retr, w_ro, retout, NTOK, Dc, Dc);

    // 9. gate
    gate_kernel<<<NTOK, 512>>>(xn, w_gate, b_gate, gmean);

    // 10. combine
    combine_kernel<<<NELEM / 256, 256>>>(x, localp, retout, gmean, out);
}

// round 7
// speedup vs baseline: 1.3029x; 1.3029x over previous
#include <cuda_runtime.h>
#include <cuda_bf16.h>
#include <math.h>

// Problem constants
#define Bc   2
#define Tc   2048
#define Dc   1024
#define Hc   16
#define Kc   64
#define Vc   64
#define Wc   256
#define BANKc 64
#define CUEc 50250
#define NTOK (Bc*Tc)            // 4096
#define NELEM (Bc*Tc*Dc)        // 4,194,304

// ---------------- scratch buffers (static device memory) ----------------
__device__ float g_xn[NELEM];
__device__ float g_q[NELEM];
__device__ float g_k[NELEM];
__device__ float g_v[NELEM];
__device__ float g_attn[NELEM];
__device__ float g_localp[NELEM];
__device__ float g_qg[NELEM];
__device__ float g_retr[NELEM];
__device__ float g_retout[NELEM];
__device__ float g_gmean[NTOK];

// ---------------- helpers ----------------
__device__ __forceinline__ float warpSum(float v) {
    #pragma unroll
    for (int o = 16; o; o >>= 1) v += __shfl_xor_sync(0xffffffffu, v, o);
    return v;
}
__device__ __forceinline__ float warpMax(float v) {
    #pragma unroll
    for (int o = 16; o; o >>= 1) v = fmaxf(v, __shfl_xor_sync(0xffffffffu, v, o));
    return v;
}

// ---------------- RMSNorm ----------------
__global__ __launch_bounds__(256) void rmsnorm_kernel(
    const float* __restrict__ x, const float* __restrict__ w, float* __restrict__ xn)
{
    int n = blockIdx.x;
    const float* xp = x + (size_t)n * Dc;
    float s = 0.f;
    for (int d = threadIdx.x; d < Dc; d += 256) { float v = xp[d]; s += v * v; }
    __shared__ float red[8];
    s = warpSum(s);
    int warp = threadIdx.x >> 5, lane = threadIdx.x & 31;
    if (lane == 0) red[warp] = s;
    __syncthreads();
    if (warp == 0) {
        float t = lane < 8 ? red[lane] : 0.f;
        t = warpSum(t);
        if (lane == 0) red[0] = rsqrtf(t / (float)Dc + 1e-6f);
    }
    __syncthreads();
    float inv = red[0];
    float* op = xn + (size_t)n * Dc;
    for (int d = threadIdx.x; d < Dc; d += 256) op[d] = xp[d] * inv * w[d];
}

// ---------------- GEMM: C[M,N] = A[M,Kd] @ W[N,Kd]^T ----------------
// 128x128x16 block tile, 256 threads, 8x8 per-thread micro-tile,
// double-buffered smem with register-staged prefetch, LDS.128 inner loop.
#define BM 128
#define BN 128
#define BKt 16

__global__ __launch_bounds__(256, 2) void gemm_awt(
    const float* __restrict__ A, const float* __restrict__ W,
    float* __restrict__ C, int M, int N, int Kd)
{
    __shared__ float As[2][BKt][BM];   // K-major (transposed): As[k][m]
    __shared__ float Bs[2][BKt][BN];   // Bs[k][n]

    int tid = threadIdx.x;
    int bm = blockIdx.y * BM;
    int bn = blockIdx.x * BN;

    // ---- loader mapping: each thread loads 2 float4 of A and 2 of W ----
    int lrow = tid >> 1;               // 0..127 tile row
    int kb   = (tid & 1) * 8;          // k offset 0 or 8

    const float* Aptr = A + (size_t)(bm + lrow) * Kd + kb;
    const float* Wptr = W + (size_t)(bn + lrow) * Kd + kb;

    // ---- compute mapping: 8 warps as 2(M) x 4(N); lanes 8(M) x 4(N) ----
    int warp = tid >> 5, lane = tid & 31;
    int m0 = (warp >> 2) * 64 + (lane >> 2) * 8;   // 8 rows
    int n0 = (warp & 3) * 32 + (lane & 3) * 8;     // 8 cols

    float acc[8][8] = {};
    float4 pa0, pa1, pb0, pb1;

    // first tile gmem -> regs
    pa0 = *(const float4*)(Aptr);
    pa1 = *(const float4*)(Aptr + 4);
    pb0 = *(const float4*)(Wptr);
    pb1 = *(const float4*)(Wptr + 4);

    // regs -> smem[0]
    {
        As[0][kb+0][lrow]=pa0.x; As[0][kb+1][lrow]=pa0.y; As[0][kb+2][lrow]=pa0.z; As[0][kb+3][lrow]=pa0.w;
        As[0][kb+4][lrow]=pa1.x; As[0][kb+5][lrow]=pa1.y; As[0][kb+6][lrow]=pa1.z; As[0][kb+7][lrow]=pa1.w;
        Bs[0][kb+0][lrow]=pb0.x; Bs[0][kb+1][lrow]=pb0.y; Bs[0][kb+2][lrow]=pb0.z; Bs[0][kb+3][lrow]=pb0.w;
        Bs[0][kb+4][lrow]=pb1.x; Bs[0][kb+5][lrow]=pb1.y; Bs[0][kb+6][lrow]=pb1.z; Bs[0][kb+7][lrow]=pb1.w;
    }
    __syncthreads();

    int buf = 0;
    for (int k0 = 0; k0 < Kd; k0 += BKt) {
        bool has_next = (k0 + BKt) < Kd;
        if (has_next) {
            const float* ap = Aptr + k0 + BKt;
            const float* wp = Wptr + k0 + BKt;
            pa0 = *(const float4*)(ap);
            pa1 = *(const float4*)(ap + 4);
            pb0 = *(const float4*)(wp);
            pb1 = *(const float4*)(wp + 4);
        }

        #pragma unroll
        for (int kk = 0; kk < BKt; kk++) {
            float4 a0 = *(const float4*)&As[buf][kk][m0];
            float4 a1 = *(const float4*)&As[buf][kk][m0 + 4];
            float4 b0 = *(const float4*)&Bs[buf][kk][n0];
            float4 b1 = *(const float4*)&Bs[buf][kk][n0 + 4];
            float a[8] = {a0.x,a0.y,a0.z,a0.w,a1.x,a1.y,a1.z,a1.w};
            float b[8] = {b0.x,b0.y,b0.z,b0.w,b1.x,b1.y,b1.z,b1.w};
            #pragma unroll
            for (int i = 0; i < 8; i++)
                #pragma unroll
                for (int j = 0; j < 8; j++)
                    acc[i][j] = fmaf(a[i], b[j], acc[i][j]);
        }

        if (has_next) {
            int nb = buf ^ 1;
            As[nb][kb+0][lrow]=pa0.x; As[nb][kb+1][lrow]=pa0.y; As[nb][kb+2][lrow]=pa0.z; As[nb][kb+3][lrow]=pa0.w;
            As[nb][kb+4][lrow]=pa1.x; As[nb][kb+5][lrow]=pa1.y; As[nb][kb+6][lrow]=pa1.z; As[nb][kb+7][lrow]=pa1.w;
            Bs[nb][kb+0][lrow]=pb0.x; Bs[nb][kb+1][lrow]=pb0.y; Bs[nb][kb+2][lrow]=pb0.z; Bs[nb][kb+3][lrow]=pb0.w;
            Bs[nb][kb+4][lrow]=pb1.x; Bs[nb][kb+5][lrow]=pb1.y; Bs[nb][kb+6][lrow]=pb1.z; Bs[nb][kb+7][lrow]=pb1.w;
            __syncthreads();
            buf = nb;
        }
    }

    // epilogue: float4 stores
    #pragma unroll
    for (int i = 0; i < 8; i++) {
        float* cp = C + (size_t)(bm + m0 + i) * N + bn + n0;
        *(float4*)cp       = make_float4(acc[i][0], acc[i][1], acc[i][2], acc[i][3]);
        *(float4*)(cp + 4) = make_float4(acc[i][4], acc[i][5], acc[i][6], acc[i][7]);
    }
}

// ---------------- RoPE (in-place on q and k), 8 warps/block ----------------
__global__ __launch_bounds__(256) void rope_kernel(float* __restrict__ q, float* __restrict__ k)
{
    int warp = threadIdx.x >> 5;
    int j = threadIdx.x & 31;             // 0..31
    int bth = blockIdx.x * 8 + warp;      // enumerates (b,t,h) in memory order
    int t = (bth / Hc) % Tc;
    float inv = powf(10000.0f, -(float)j / 32.0f);
    float ang = (float)t * inv;
    float c, s;
    sincosf(ang, &s, &c);                 // accurate: ang can be ~2000 rad
    float* qp = q + (size_t)bth * Kc;
    float* kp = k + (size_t)bth * Kc;
    float q1 = qp[j], q2 = qp[j + 32];
    qp[j]      = q1 * c - q2 * s;
    qp[j + 32] = q2 * c + q1 * s;
    float k1 = kp[j], k2 = kp[j + 32];
    kp[j]      = k1 * c - k2 * s;
    kp[j + 32] = k2 * c + k1 * s;
}

// ---------------- Sliding-window attention: warp per (b,h,t) ----------------
__global__ __launch_bounds__(128) void attn_kernel(
    const float* __restrict__ q, const float* __restrict__ k,
    const float* __restrict__ v, float* __restrict__ out)
{
    __shared__ float qsh[4][Kc];
    __shared__ float ssh[4][Wc + 1];
    int warp = threadIdx.x >> 5, lane = threadIdx.x & 31;
    int gidx = blockIdx.x * 4 + warp;       // ((b*H + h)*T + t)
    int t = gidx % Tc;
    int bh = gidx / Tc;
    int h = bh % Hc;
    int b = bh / Hc;

    const float* qp = q + ((size_t)(b * Tc + t) * Hc + h) * Kc;
    qsh[warp][lane]      = qp[lane];
    qsh[warp][lane + 32] = qp[lane + 32];
    __syncwarp();

    int s_start = t - Wc; if (s_start < 0) s_start = 0;
    int S = t - s_start + 1;                // <= 257

    float mloc = -1e30f;
    for (int idx = lane; idx < S; idx += 32) {
        int s = s_start + idx;
        const float4* kp4 = (const float4*)(k + ((size_t)(b * Tc + s) * Hc + h) * Kc);
        float d = 0.f;
        #pragma unroll
        for (int kk = 0; kk < 16; kk++) {
            float4 kv = kp4[kk];
            d = fmaf(qsh[warp][4 * kk + 0], kv.x, d);
            d = fmaf(qsh[warp][4 * kk + 1], kv.y, d);
            d = fmaf(qsh[warp][4 * kk + 2], kv.z, d);
            d = fmaf(qsh[warp][4 * kk + 3], kv.w, d);
        }
        d *= 0.125f;                        // K^-0.5
        ssh[warp][idx] = d;
        mloc = fmaxf(mloc, d);
    }
    float mx = warpMax(mloc);
    __syncwarp();
    float sl = 0.f;
    for (int idx = lane; idx < S; idx += 32) {
        float e = __expf(ssh[warp][idx] - mx);
        ssh[warp][idx] = e;
        sl += e;
    }
    float ssum = warpSum(sl);
    float invs = 1.0f / ssum;
    __syncwarp();

    int d0 = lane * 2;
    float o0 = 0.f, o1 = 0.f;
    for (int idx = 0; idx < S; idx++) {
        float p = ssh[warp][idx];
        const float2* vp = (const float2*)(v + ((size_t)(b * Tc + s_start + idx) * Hc + h) * Kc);
        float2 v2 = vp[lane];
        o0 = fmaf(p, v2.x, o0);
        o1 = fmaf(p, v2.y, o1);
    }
    float* op = out + ((size_t)(b * Tc + t) * Hc + h) * Vc;
    op[d0]     = o0 * invs;
    op[d0 + 1] = o1 * invs;
}

// ---------------- gather-replace q_g from key_bank ----------------
__global__ __launch_bounds__(256) void gather_kernel(
    const int* __restrict__ input_ids, const float* __restrict__ key_bank,
    float* __restrict__ qg)
{
    int n = blockIdx.x;
    int idx = input_ids[n] - CUEc;
    if (idx < 0 || idx >= BANKc) return;
    for (int i = threadIdx.x; i < Hc * Kc; i += 256) {
        int h = i >> 6, kk = i & 63;
        qg[(size_t)n * (Hc * Kc) + i] = key_bank[((size_t)h * BANKc + idx) * Kc + kk];
    }
}

// ---------------- retrieval: retrieved[b,t,h,v] = sum_k state[b,h,k,v]*qg[b,t,h,k] ----
__global__ __launch_bounds__(256) void retrieve_kernel(
    const float* __restrict__ state, const float* __restrict__ qg, float* __restrict__ out)
{
    __shared__ float st[Kc * Vc];           // 16 KB
    __shared__ float qsh[8][Kc];
    int bh = blockIdx.x;                    // b*H + h
    int b = bh / Hc, h = bh % Hc;
    const float* sp = state + (size_t)bh * Kc * Vc;
    for (int i = threadIdx.x; i < Kc * Vc; i += 256) st[i] = sp[i];
    int warp = threadIdx.x >> 5, lane = threadIdx.x & 31;
    int t = blockIdx.y * 8 + warp;
    const float* qp = qg + ((size_t)(b * Tc + t) * Hc + h) * Kc;
    qsh[warp][lane]      = qp[lane];
    qsh[warp][lane + 32] = qp[lane + 32];
    __syncthreads();
    float o0 = 0.f, o1 = 0.f;
    #pragma unroll
    for (int kk = 0; kk < Kc; kk++) {
        float qv = qsh[warp][kk];
        float2 s2 = ((const float2*)(st + kk * Vc))[lane];
        o0 = fmaf(qv, s2.x, o0);
        o1 = fmaf(qv, s2.y, o1);
    }
    float* op = out + ((size_t)(b * Tc + t) * Hc + h) * Vc;
    op[lane * 2]     = o0;
    op[lane * 2 + 1] = o1;
}

// ---------------- gate mean: sigmoid(xn @ w_gate^T + b_gate), mean over H ----------
__global__ __launch_bounds__(512) void gate_kernel(
    const float* __restrict__ xn, const float* __restrict__ w_gate,
    const float* __restrict__ b_gate, float* __restrict__ gmean)
{
    __shared__ float gsh[Hc];
    int n = blockIdx.x;
    int warp = threadIdx.x >> 5, lane = threadIdx.x & 31;   // warp == head
    const float* xp = xn + (size_t)n * Dc;
    const float* wp = w_gate + (size_t)warp * Dc;
    float s = 0.f;
    for (int d = lane; d < Dc; d += 32) s = fmaf(xp[d], wp[d], s);
    s = warpSum(s);
    if (lane == 0) gsh[warp] = 1.0f / (1.0f + __expf(-(s + b_gate[warp])));
    __syncthreads();
    if (threadIdx.x == 0) {
        float acc = 0.f;
        #pragma unroll
        for (int h = 0; h < Hc; h++) acc += gsh[h];
        gmean[n] = acc / (float)Hc;
    }
}

// ---------------- final combine ----------------
__global__ __launch_bounds__(256) void combine_kernel(
    const float* __restrict__ x, const float* __restrict__ localp,
    const float* __restrict__ retout, const float* __restrict__ gmean,
    float* __restrict__ out)
{
    int i = blockIdx.x * 256 + threadIdx.x;
    int n = i >> 10;                        // i / D
    out[i] = x[i] + 0.3f * localp[i] + gmean[n] * retout[i];
}

// ---------------- launch ----------------
extern "C" void kernel_launch(void* const* d_in, const int* in_sizes, int n_in,
                              void* d_out, int out_size)
{
    const float* x         = (const float*)d_in[0];
    const float* gdn_state = (const float*)d_in[1];
    const int*   input_ids = (const int*)  d_in[2];
    const float* key_bank  = (const float*)d_in[3];
    const float* norm_w    = (const float*)d_in[4];
    const float* wq        = (const float*)d_in[5];
    const float* wk        = (const float*)d_in[6];
    const float* wv        = (const float*)d_in[7];
    const float* wo        = (const float*)d_in[8];
    const float* w_gq      = (const float*)d_in[9];
    const float* w_ro      = (const float*)d_in[10];
    const float* w_gate    = (const float*)d_in[11];
    const float* b_gate    = (const float*)d_in[12];
    float* out = (float*)d_out;

    float *xn, *q, *k, *v, *attn, *localp, *qg, *retr, *retout, *gmean;
    cudaGetSymbolAddress((void**)&xn,     g_xn);
    cudaGetSymbolAddress((void**)&q,      g_q);
    cudaGetSymbolAddress((void**)&k,      g_k);
    cudaGetSymbolAddress((void**)&v,      g_v);
    cudaGetSymbolAddress((void**)&attn,   g_attn);
    cudaGetSymbolAddress((void**)&localp, g_localp);
    cudaGetSymbolAddress((void**)&qg,     g_qg);
    cudaGetSymbolAddress((void**)&retr,   g_retr);
    cudaGetSymbolAddress((void**)&retout, g_retout);
    cudaGetSymbolAddress((void**)&gmean,  g_gmean);

    // 1. RMSNorm
    rmsnorm_kernel<<<NTOK, 256>>>(x, norm_w, xn);

    dim3 ggrid(Dc / BN, NTOK / BM);     // (8, 32)
    // 2. projections
    gemm_awt<<<ggrid, 256>>>(xn, wq,   q,  NTOK, Dc, Dc);
    gemm_awt<<<ggrid, 256>>>(xn, wk,   k,  NTOK, Dc, Dc);
    gemm_awt<<<ggrid, 256>>>(xn, wv,   v,  NTOK, Dc, Dc);
    gemm_awt<<<ggrid, 256>>>(xn, w_gq, qg, NTOK, Dc, Dc);

    // 3. RoPE on q,k
    rope_kernel<<<Bc * Tc * Hc / 8, 256>>>(q, k);

    // 4. attention
    attn_kernel<<<Bc * Hc * Tc / 4, 128>>>(q, k, v, attn);

    // 5. local output projection
    gemm_awt<<<ggrid, 256>>>(attn, wo, localp, NTOK, Dc, Dc);

    // 6. gather-replace q_g
    gather_kernel<<<NTOK, 256>>>(input_ids, key_bank, qg);

    // 7. retrieval einsum
    {
        dim3 rg(Bc * Hc, Tc / 8);
        retrieve_kernel<<<rg, 256>>>(gdn_state, qg, retr);
    }

    // 8. retrieval output projection
    gemm_awt<<<ggrid, 256>>>(retr, w_ro, retout, NTOK, Dc, Dc);

    // 9. gate
    gate_kernel<<<NTOK, 512>>>(xn, w_gate, b_gate, gmean);

    // 10. combine
    combine_kernel<<<NELEM / 256, 256>>>(x, localp, retout, gmean, out);
}

// round 8
// speedup vs baseline: 1.7820x; 1.3677x over previous
#include <cuda_runtime.h>
#include <cuda_bf16.h>
#include <math.h>
#include <stdint.h>

// Problem constants
#define Bc   2
#define Tc   2048
#define Dc   1024
#define Hc   16
#define Kc   64
#define Vc   64
#define Wc   256
#define BANKc 64
#define CUEc 50250
#define NTOK (Bc*Tc)            // 4096
#define NELEM (Bc*Tc*Dc)        // 4,194,304

// ---------------- scratch buffers (static device memory) ----------------
__device__ float g_xn[NELEM];
__device__ float g_q[NELEM];
__device__ float g_k[NELEM];
__device__ float g_v[NELEM];
__device__ float g_localp[NELEM];
__device__ float g_qg[NELEM];
__device__ float g_retr[NELEM];
__device__ float g_retout[NELEM];
__device__ float g_gmean[NTOK];
// bf16 buffers
__device__ __nv_bfloat16 g_xnb[NELEM];
__device__ __nv_bfloat16 g_attnb[NELEM];
__device__ __nv_bfloat16 g_wqb[Dc*Dc];
__device__ __nv_bfloat16 g_wkb[Dc*Dc];
__device__ __nv_bfloat16 g_wvb[Dc*Dc];
__device__ __nv_bfloat16 g_wob[Dc*Dc];

// ---------------- helpers ----------------
__device__ __forceinline__ float warpSum(float v) {
    #pragma unroll
    for (int o = 16; o; o >>= 1) v += __shfl_xor_sync(0xffffffffu, v, o);
    return v;
}
__device__ __forceinline__ float warpMax(float v) {
    #pragma unroll
    for (int o = 16; o; o >>= 1) v = fmaxf(v, __shfl_xor_sync(0xffffffffu, v, o));
    return v;
}

#define CP16(dst, src) asm volatile("cp.async.cg.shared.global [%0], [%1], 16;\n" :: "r"(dst), "l"(src))
#define LDSM4(r0,r1,r2,r3,addr) \
    asm volatile("ldmatrix.sync.aligned.m8n8.x4.shared.b16 {%0,%1,%2,%3}, [%4];" \
                 : "=r"(r0),"=r"(r1),"=r"(r2),"=r"(r3) : "r"(addr))
#define MMA16816(d0,d1,d2,d3,a0,a1,a2,a3,b0,b1) \
    asm volatile("mma.sync.aligned.m16n8k16.row.col.f32.bf16.bf16.f32 " \
                 "{%0,%1,%2,%3}, {%4,%5,%6,%7}, {%8,%9}, {%0,%1,%2,%3};" \
                 : "+f"(d0),"+f"(d1),"+f"(d2),"+f"(d3) \
                 : "r"(a0),"r"(a1),"r"(a2),"r"(a3),"r"(b0),"r"(b1))

// ---------------- fp32 -> bf16 convert (float4 / bf16x2) ----------------
__global__ __launch_bounds__(256) void cvt_bf16_kernel(
    const float* __restrict__ in, __nv_bfloat16* __restrict__ out)
{
    int i = blockIdx.x * 256 + threadIdx.x;
    float4 v = ((const float4*)in)[i];
    __nv_bfloat162 p0 = __floats2bfloat162_rn(v.x, v.y);
    __nv_bfloat162 p1 = __floats2bfloat162_rn(v.z, v.w);
    ((__nv_bfloat162*)out)[i*2]   = p0;
    ((__nv_bfloat162*)out)[i*2+1] = p1;
}

// ---------------- RMSNorm (fp32 + bf16 outputs) ----------------
__global__ __launch_bounds__(256) void rmsnorm_kernel(
    const float* __restrict__ x, const float* __restrict__ w,
    float* __restrict__ xn, __nv_bfloat16* __restrict__ xnb)
{
    int n = blockIdx.x;
    const float* xp = x + (size_t)n * Dc;
    float s = 0.f;
    for (int d = threadIdx.x; d < Dc; d += 256) { float v = xp[d]; s += v * v; }
    __shared__ float red[8];
    s = warpSum(s);
    int warp = threadIdx.x >> 5, lane = threadIdx.x & 31;
    if (lane == 0) red[warp] = s;
    __syncthreads();
    if (warp == 0) {
        float t = lane < 8 ? red[lane] : 0.f;
        t = warpSum(t);
        if (lane == 0) red[0] = rsqrtf(t / (float)Dc + 1e-6f);
    }
    __syncthreads();
    float inv = red[0];
    float* op = xn + (size_t)n * Dc;
    __nv_bfloat16* ob = xnb + (size_t)n * Dc;
    for (int d = threadIdx.x; d < Dc; d += 256) {
        float v = xp[d] * inv * w[d];
        op[d] = v;
        ob[d] = __float2bfloat16(v);
    }
}

// ---------------- bf16 tensor-core GEMM: C[M,N] = A[M,K] @ W[N,K]^T ----------------
// 128x128x64 tile, 256 threads (8 warps, 2x4), mma.m16n8k16, cp.async double buffer.
#define TBM 128
#define TBN 128
#define TBK 64

__global__ __launch_bounds__(256, 2) void gemm_bf16(
    const __nv_bfloat16* __restrict__ A, const __nv_bfloat16* __restrict__ W,
    float* __restrict__ C, int M, int N, int Kd)
{
    extern __shared__ __nv_bfloat16 sm[];
    // As[2][128*64], Bs[2][128*64]  (each buf 8192 bf16 = 16KB)
    const int TILE = TBM * TBK;
    uint32_t sA = (uint32_t)__cvta_generic_to_shared(sm);
    uint32_t sB = sA + 2 * TILE * 2;  // bytes

    int tid = threadIdx.x;
    int bm = blockIdx.y * TBM, bn = blockIdx.x * TBN;
    int warp = tid >> 5, lane = tid & 31;
    int wm = (warp >> 2) * 64;      // 0 or 64
    int wn = (warp & 3) * 32;       // 0,32,64,96

    // loader: 2 threads per row, 4 chunks (16B each) per thread
    int lrow = tid >> 1;
    int cbase = (tid & 1) * 4;
    int r7 = lrow & 7;
    const __nv_bfloat16* Ag = A + (size_t)(bm + lrow) * Kd;
    const __nv_bfloat16* Wg = W + (size_t)(bn + lrow) * Kd;
    uint32_t daBase = sA + (uint32_t)(lrow * TBK) * 2;
    uint32_t dbBase = sB + (uint32_t)(lrow * TBK) * 2;

    // fragment lane mapping
    int arow = lane & 15;
    int ahk  = lane >> 4;                          // 0/1 -> k chunk
    int bnr  = (lane & 7) + ((lane >> 4) << 3);    // n within 16-block
    int bhk  = (lane >> 3) & 1;                    // k chunk

    float acc[4][4][4] = {};

    const int NT = 1024 / TBK;  // Kd==1024 always here; keep literal for unroll

    // prologue: issue tile 0
    {
        #pragma unroll
        for (int c = 0; c < 4; c++) {
            int ch = cbase + c;
            int pch = ch ^ r7;
            CP16(daBase + (uint32_t)pch * 16, Ag + ch * 8);
            CP16(dbBase + (uint32_t)pch * 16, Wg + ch * 8);
        }
        asm volatile("cp.async.commit_group;\n" ::);
    }

    int buf = 0;
    for (int t = 0; t < NT; t++) {
        if (t + 1 < NT) {
            int k0 = (t + 1) * TBK;
            uint32_t da = daBase + (uint32_t)((buf ^ 1) * TILE) * 2;
            uint32_t db = dbBase + (uint32_t)((buf ^ 1) * TILE) * 2;
            #pragma unroll
            for (int c = 0; c < 4; c++) {
                int ch = cbase + c;
                int pch = ch ^ r7;
                CP16(da + (uint32_t)pch * 16, Ag + k0 + ch * 8);
                CP16(db + (uint32_t)pch * 16, Wg + k0 + ch * 8);
            }
            asm volatile("cp.async.commit_group;\n" ::);
            asm volatile("cp.async.wait_group 1;\n" ::: "memory");
        } else {
            asm volatile("cp.async.wait_group 0;\n" ::: "memory");
        }
        __syncthreads();

        uint32_t aBuf = sA + (uint32_t)(buf * TILE) * 2;
        uint32_t bBuf = sB + (uint32_t)(buf * TILE) * 2;

        #pragma unroll
        for (int ks = 0; ks < 4; ks++) {
            uint32_t af[4][4];
            #pragma unroll
            for (int i = 0; i < 4; i++) {
                int row = wm + i * 16 + arow;
                int ch = ks * 2 + ahk;
                uint32_t addr = aBuf + (uint32_t)(row * TBK + ((ch ^ (row & 7)) << 3)) * 2;
                LDSM4(af[i][0], af[i][1], af[i][2], af[i][3], addr);
            }
            uint32_t bf[4][2];
            #pragma unroll
            for (int jp = 0; jp < 2; jp++) {
                int n = wn + jp * 16 + bnr;
                int ch = ks * 2 + bhk;
                uint32_t addr = bBuf + (uint32_t)(n * TBK + ((ch ^ (n & 7)) << 3)) * 2;
                LDSM4(bf[jp*2][0], bf[jp*2][1], bf[jp*2+1][0], bf[jp*2+1][1], addr);
            }
            #pragma unroll
            for (int i = 0; i < 4; i++)
                #pragma unroll
                for (int j = 0; j < 4; j++)
                    MMA16816(acc[i][j][0], acc[i][j][1], acc[i][j][2], acc[i][j][3],
                             af[i][0], af[i][1], af[i][2], af[i][3],
                             bf[j][0], bf[j][1]);
        }
        __syncthreads();
        buf ^= 1;
    }

    // epilogue: each thread owns rows (g, g+8), cols (2t, 2t+1) per 16x8 block
    int g = lane >> 2, t2 = lane & 3;
    #pragma unroll
    for (int i = 0; i < 4; i++) {
        int row0 = bm + wm + i * 16 + g;
        #pragma unroll
        for (int j = 0; j < 4; j++) {
            int col = bn + wn + j * 8 + t2 * 2;
            *(float2*)(C + (size_t)row0 * N + col)       = make_float2(acc[i][j][0], acc[i][j][1]);
            *(float2*)(C + (size_t)(row0 + 8) * N + col) = make_float2(acc[i][j][2], acc[i][j][3]);
        }
    }
}

// ---------------- fp32 GEMM (retrieval path): C[M,N] = A[M,K] @ W[N,K]^T ----------------
#define BM 128
#define BN 128
#define BKt 16
__global__ __launch_bounds__(256, 2) void gemm_awt(
    const float* __restrict__ A, const float* __restrict__ W,
    float* __restrict__ C, int M, int N, int Kd)
{
    __shared__ float As[2][BKt][BM];
    __shared__ float Bs[2][BKt][BN];
    int tid = threadIdx.x;
    int bm = blockIdx.y * BM;
    int bn = blockIdx.x * BN;
    int lrow = tid >> 1;
    int kb   = (tid & 1) * 8;
    const float* Aptr = A + (size_t)(bm + lrow) * Kd + kb;
    const float* Wptr = W + (size_t)(bn + lrow) * Kd + kb;
    int warp = tid >> 5, lane = tid & 31;
    int m0 = (warp >> 2) * 64 + (lane >> 2) * 8;
    int n0 = (warp & 3) * 32 + (lane & 3) * 8;
    float acc[8][8] = {};
    float4 pa0, pa1, pb0, pb1;
    pa0 = *(const float4*)(Aptr);
    pa1 = *(const float4*)(Aptr + 4);
    pb0 = *(const float4*)(Wptr);
    pb1 = *(const float4*)(Wptr + 4);
    {
        As[0][kb+0][lrow]=pa0.x; As[0][kb+1][lrow]=pa0.y; As[0][kb+2][lrow]=pa0.z; As[0][kb+3][lrow]=pa0.w;
        As[0][kb+4][lrow]=pa1.x; As[0][kb+5][lrow]=pa1.y; As[0][kb+6][lrow]=pa1.z; As[0][kb+7][lrow]=pa1.w;
        Bs[0][kb+0][lrow]=pb0.x; Bs[0][kb+1][lrow]=pb0.y; Bs[0][kb+2][lrow]=pb0.z; Bs[0][kb+3][lrow]=pb0.w;
        Bs[0][kb+4][lrow]=pb1.x; Bs[0][kb+5][lrow]=pb1.y; Bs[0][kb+6][lrow]=pb1.z; Bs[0][kb+7][lrow]=pb1.w;
    }
    __syncthreads();
    int buf = 0;
    for (int k0 = 0; k0 < Kd; k0 += BKt) {
        bool has_next = (k0 + BKt) < Kd;
        if (has_next) {
            const float* ap = Aptr + k0 + BKt;
            const float* wp = Wptr + k0 + BKt;
            pa0 = *(const float4*)(ap);
            pa1 = *(const float4*)(ap + 4);
            pb0 = *(const float4*)(wp);
            pb1 = *(const float4*)(wp + 4);
        }
        #pragma unroll
        for (int kk = 0; kk < BKt; kk++) {
            float4 a0 = *(const float4*)&As[buf][kk][m0];
            float4 a1 = *(const float4*)&As[buf][kk][m0 + 4];
            float4 b0 = *(const float4*)&Bs[buf][kk][n0];
            float4 b1 = *(const float4*)&Bs[buf][kk][n0 + 4];
            float a[8] = {a0.x,a0.y,a0.z,a0.w,a1.x,a1.y,a1.z,a1.w};
            float b[8] = {b0.x,b0.y,b0.z,b0.w,b1.x,b1.y,b1.z,b1.w};
            #pragma unroll
            for (int i = 0; i < 8; i++)
                #pragma unroll
                for (int j = 0; j < 8; j++)
                    acc[i][j] = fmaf(a[i], b[j], acc[i][j]);
        }
        if (has_next) {
            int nb = buf ^ 1;
            As[nb][kb+0][lrow]=pa0.x; As[nb][kb+1][lrow]=pa0.y; As[nb][kb+2][lrow]=pa0.z; As[nb][kb+3][lrow]=pa0.w;
            As[nb][kb+4][lrow]=pa1.x; As[nb][kb+5][lrow]=pa1.y; As[nb][kb+6][lrow]=pa1.z; As[nb][kb+7][lrow]=pa1.w;
            Bs[nb][kb+0][lrow]=pb0.x; Bs[nb][kb+1][lrow]=pb0.y; Bs[nb][kb+2][lrow]=pb0.z; Bs[nb][kb+3][lrow]=pb0.w;
            Bs[nb][kb+4][lrow]=pb1.x; Bs[nb][kb+5][lrow]=pb1.y; Bs[nb][kb+6][lrow]=pb1.z; Bs[nb][kb+7][lrow]=pb1.w;
            __syncthreads();
            buf = nb;
        }
    }
    #pragma unroll
    for (int i = 0; i < 8; i++) {
        float* cp = C + (size_t)(bm + m0 + i) * N + bn + n0;
        *(float4*)cp       = make_float4(acc[i][0], acc[i][1], acc[i][2], acc[i][3]);
        *(float4*)(cp + 4) = make_float4(acc[i][4], acc[i][5], acc[i][6], acc[i][7]);
    }
}

// ---------------- RoPE (in-place on q and k), 8 warps/block ----------------
__global__ __launch_bounds__(256) void rope_kernel(float* __restrict__ q, float* __restrict__ k)
{
    int warp = threadIdx.x >> 5;
    int j = threadIdx.x & 31;
    int bth = blockIdx.x * 8 + warp;
    int t = (bth / Hc) % Tc;
    float inv = powf(10000.0f, -(float)j / 32.0f);
    float ang = (float)t * inv;
    float c, s;
    sincosf(ang, &s, &c);
    float* qp = q + (size_t)bth * Kc;
    float* kp = k + (size_t)bth * Kc;
    float q1 = qp[j], q2 = qp[j + 32];
    qp[j]      = q1 * c - q2 * s;
    qp[j + 32] = q2 * c + q1 * s;
    float k1 = kp[j], k2 = kp[j + 32];
    kp[j]      = k1 * c - k2 * s;
    kp[j + 32] = k2 * c + k1 * s;
}

// ---------------- Sliding-window attention: warp per (b,h,t), bf16 output ------
__global__ __launch_bounds__(128) void attn_kernel(
    const float* __restrict__ q, const float* __restrict__ k,
    const float* __restrict__ v, __nv_bfloat16* __restrict__ out)
{
    __shared__ float qsh[4][Kc];
    __shared__ float ssh[4][Wc + 1];
    int warp = threadIdx.x >> 5, lane = threadIdx.x & 31;
    int gidx = blockIdx.x * 4 + warp;
    int t = gidx % Tc;
    int bh = gidx / Tc;
    int h = bh % Hc;
    int b = bh / Hc;

    const float* qp = q + ((size_t)(b * Tc + t) * Hc + h) * Kc;
    qsh[warp][lane]      = qp[lane];
    qsh[warp][lane + 32] = qp[lane + 32];
    __syncwarp();

    int s_start = t - Wc; if (s_start < 0) s_start = 0;
    int S = t - s_start + 1;

    float mloc = -1e30f;
    for (int idx = lane; idx < S; idx += 32) {
        int s = s_start + idx;
        const float4* kp4 = (const float4*)(k + ((size_t)(b * Tc + s) * Hc + h) * Kc);
        float d = 0.f;
        #pragma unroll
        for (int kk = 0; kk < 16; kk++) {
            float4 kv = kp4[kk];
            d = fmaf(qsh[warp][4 * kk + 0], kv.x, d);
            d = fmaf(qsh[warp][4 * kk + 1], kv.y, d);
            d = fmaf(qsh[warp][4 * kk + 2], kv.z, d);
            d = fmaf(qsh[warp][4 * kk + 3], kv.w, d);
        }
        d *= 0.125f;
        ssh[warp][idx] = d;
        mloc = fmaxf(mloc, d);
    }
    float mx = warpMax(mloc);
    __syncwarp();
    float sl = 0.f;
    for (int idx = lane; idx < S; idx += 32) {
        float e = __expf(ssh[warp][idx] - mx);
        ssh[warp][idx] = e;
        sl += e;
    }
    float ssum = warpSum(sl);
    float invs = 1.0f / ssum;
    __syncwarp();

    float o0 = 0.f, o1 = 0.f;
    for (int idx = 0; idx < S; idx++) {
        float p = ssh[warp][idx];
        const float2* vp = (const float2*)(v + ((size_t)(b * Tc + s_start + idx) * Hc + h) * Kc);
        float2 v2 = vp[lane];
        o0 = fmaf(p, v2.x, o0);
        o1 = fmaf(p, v2.y, o1);
    }
    __nv_bfloat162* op = (__nv_bfloat162*)(out + ((size_t)(b * Tc + t) * Hc + h) * Vc);
    op[lane] = __floats2bfloat162_rn(o0 * invs, o1 * invs);
}

// ---------------- gather-replace q_g from key_bank ----------------
__global__ __launch_bounds__(256) void gather_kernel(
    const int* __restrict__ input_ids, const float* __restrict__ key_bank,
    float* __restrict__ qg)
{
    int n = blockIdx.x;
    int idx = input_ids[n] - CUEc;
    if (idx < 0 || idx >= BANKc) return;
    for (int i = threadIdx.x; i < Hc * Kc; i += 256) {
        int h = i >> 6, kk = i & 63;
        qg[(size_t)n * (Hc * Kc) + i] = key_bank[((size_t)h * BANKc + idx) * Kc + kk];
    }
}

// ---------------- retrieval: retrieved[b,t,h,v] = sum_k state[b,h,k,v]*qg[b,t,h,k] ----
__global__ __launch_bounds__(256) void retrieve_kernel(
    const float* __restrict__ state, const float* __restrict__ qg, float* __restrict__ out)
{
    __shared__ float st[Kc * Vc];
    __shared__ float qsh[8][Kc];
    int bh = blockIdx.x;
    int b = bh / Hc, h = bh % Hc;
    const float* sp = state + (size_t)bh * Kc * Vc;
    for (int i = threadIdx.x; i < Kc * Vc; i += 256) st[i] = sp[i];
    int warp = threadIdx.x >> 5, lane = threadIdx.x & 31;
    int t = blockIdx.y * 8 + warp;
    const float* qp = qg + ((size_t)(b * Tc + t) * Hc + h) * Kc;
    qsh[warp][lane]      = qp[lane];
    qsh[warp][lane + 32] = qp[lane + 32];
    __syncthreads();
    float o0 = 0.f, o1 = 0.f;
    #pragma unroll
    for (int kk = 0; kk < Kc; kk++) {
        float qv = qsh[warp][kk];
        float2 s2 = ((const float2*)(st + kk * Vc))[lane];
        o0 = fmaf(qv, s2.x, o0);
        o1 = fmaf(qv, s2.y, o1);
    }
    float* op = out + ((size_t)(b * Tc + t) * Hc + h) * Vc;
    op[lane * 2]     = o0;
    op[lane * 2 + 1] = o1;
}

// ---------------- gate mean ----------------
__global__ __launch_bounds__(512) void gate_kernel(
    const float* __restrict__ xn, const float* __restrict__ w_gate,
    const float* __restrict__ b_gate, float* __restrict__ gmean)
{
    __shared__ float gsh[Hc];
    int n = blockIdx.x;
    int warp = threadIdx.x >> 5, lane = threadIdx.x & 31;
    const float* xp = xn + (size_t)n * Dc;
    const float* wp = w_gate + (size_t)warp * Dc;
    float s = 0.f;
    for (int d = lane; d < Dc; d += 32) s = fmaf(xp[d], wp[d], s);
    s = warpSum(s);
    if (lane == 0) gsh[warp] = 1.0f / (1.0f + __expf(-(s + b_gate[warp])));
    __syncthreads();
    if (threadIdx.x == 0) {
        float acc = 0.f;
        #pragma unroll
        for (int h = 0; h < Hc; h++) acc += gsh[h];
        gmean[n] = acc / (float)Hc;
    }
}

// ---------------- final combine ----------------
__global__ __launch_bounds__(256) void combine_kernel(
    const float* __restrict__ x, const float* __restrict__ localp,
    const float* __restrict__ retout, const float* __restrict__ gmean,
    float* __restrict__ out)
{
    int i = blockIdx.x * 256 + threadIdx.x;
    int n = i >> 10;
    out[i] = x[i] + 0.3f * localp[i] + gmean[n] * retout[i];
}

// ---------------- launch ----------------
extern "C" void kernel_launch(void* const* d_in, const int* in_sizes, int n_in,
                              void* d_out, int out_size)
{
    const float* x         = (const float*)d_in[0];
    const float* gdn_state = (const float*)d_in[1];
    const int*   input_ids = (const int*)  d_in[2];
    const float* key_bank  = (const float*)d_in[3];
    const float* norm_w    = (const float*)d_in[4];
    const float* wq        = (const float*)d_in[5];
    const float* wk        = (const float*)d_in[6];
    const float* wv        = (const float*)d_in[7];
    const float* wo        = (const float*)d_in[8];
    const float* w_gq      = (const float*)d_in[9];
    const float* w_ro      = (const float*)d_in[10];
    const float* w_gate    = (const float*)d_in[11];
    const float* b_gate    = (const float*)d_in[12];
    float* out = (float*)d_out;

    float *xn, *q, *k, *v, *localp, *qg, *retr, *retout, *gmean;
    __nv_bfloat16 *xnb, *attnb, *wqb, *wkb, *wvb, *wob;
    cudaGetSymbolAddress((void**)&xn,     g_xn);
    cudaGetSymbolAddress((void**)&q,      g_q);
    cudaGetSymbolAddress((void**)&k,      g_k);
    cudaGetSymbolAddress((void**)&v,      g_v);
    cudaGetSymbolAddress((void**)&localp, g_localp);
    cudaGetSymbolAddress((void**)&qg,     g_qg);
    cudaGetSymbolAddress((void**)&retr,   g_retr);
    cudaGetSymbolAddress((void**)&retout, g_retout);
    cudaGetSymbolAddress((void**)&gmean,  g_gmean);
    cudaGetSymbolAddress((void**)&xnb,    g_xnb);
    cudaGetSymbolAddress((void**)&attnb,  g_attnb);
    cudaGetSymbolAddress((void**)&wqb,    g_wqb);
    cudaGetSymbolAddress((void**)&wkb,    g_wkb);
    cudaGetSymbolAddress((void**)&wvb,    g_wvb);
    cudaGetSymbolAddress((void**)&wob,    g_wob);

    cudaFuncSetAttribute(gemm_bf16, cudaFuncAttributeMaxDynamicSharedMemorySize, 65536);

    // 0. weight conversions (fp32 -> bf16)
    {
        int blocks = (Dc * Dc) / (256 * 4);   // 1024 blocks
        cvt_bf16_kernel<<<blocks, 256>>>(wq, wqb);
        cvt_bf16_kernel<<<blocks, 256>>>(wk, wkb);
        cvt_bf16_kernel<<<blocks, 256>>>(wv, wvb);
        cvt_bf16_kernel<<<blocks, 256>>>(wo, wob);
    }

    // 1. RMSNorm (fp32 + bf16)
    rmsnorm_kernel<<<NTOK, 256>>>(x, norm_w, xn, xnb);

    dim3 tgrid(Dc / TBN, NTOK / TBM);   // (8, 32)
    // 2. projections (bf16 tensor core)
    gemm_bf16<<<tgrid, 256, 65536>>>(xnb, wqb, q, NTOK, Dc, Dc);
    gemm_bf16<<<tgrid, 256, 65536>>>(xnb, wkb, k, NTOK, Dc, Dc);
    gemm_bf16<<<tgrid, 256, 65536>>>(xnb, wvb, v, NTOK, Dc, Dc);

    // q_g projection stays fp32 (retrieval path accuracy)
    dim3 fgrid(Dc / BN, NTOK / BM);
    gemm_awt<<<fgrid, 256>>>(xn, w_gq, qg, NTOK, Dc, Dc);

    // 3. RoPE on q,k
    rope_kernel<<<Bc * Tc * Hc / 8, 256>>>(q, k);

    // 4. attention (writes bf16)
    attn_kernel<<<Bc * Hc * Tc / 4, 128>>>(q, k, v, attnb);

    // 5. local output projection (bf16 tensor core)
    gemm_bf16<<<tgrid, 256, 65536>>>(attnb, wob, localp, NTOK, Dc, Dc);

    // 6. gather-replace q_g
    gather_kernel<<<NTOK, 256>>>(input_ids, key_bank, qg);

    // 7. retrieval einsum
    {
        dim3 rg(Bc * Hc, Tc / 8);
        retrieve_kernel<<<rg, 256>>>(gdn_state, qg, retr);
    }

    // 8. retrieval output projection (fp32)
    gemm_awt<<<fgrid, 256>>>(retr, w_ro, retout, NTOK, Dc, Dc);

    // 9. gate
    gate_kernel<<<NTOK, 512>>>(xn, w_gate, b_gate, gmean);

    // 10. combine
    combine_kernel<<<NELEM / 256, 256>>>(x, localp, retout, gmean, out);
}

// round 15
// speedup vs baseline: 4.1226x; 2.3135x over previous
#include <cuda_runtime.h>
#include <cuda_bf16.h>
#include <math.h>
#include <stdint.h>

// Problem constants
#define Bc   2
#define Tc   2048
#define Dc   1024
#define Hc   16
#define Kc   64
#define Vc   64
#define Wc   256
#define BANKc 64
#define CUEc 50250
#define NTOK (Bc*Tc)            // 4096
#define NELEM (Bc*Tc*Dc)        // 4,194,304

// ---------------- scratch buffers (static device memory) ----------------
__device__ float g_xn[NELEM];
__device__ float g_q[NELEM];
__device__ float g_k[NELEM];
__device__ float g_v[NELEM];
__device__ float g_localp[NELEM];
__device__ float g_qg[NELEM];
__device__ float g_retout[NELEM];
__device__ float g_gmean[NTOK];
// bf16 buffers
__device__ __nv_bfloat16 g_xnb[NELEM];     // hi(xn)
__device__ __nv_bfloat16 g_xnlo[NELEM];    // lo(xn)
__device__ __nv_bfloat16 g_attnb[NELEM];
__device__ __nv_bfloat16 g_retrh[NELEM];   // hi(retr)
__device__ __nv_bfloat16 g_retrlo[NELEM];  // lo(retr)
__device__ __nv_bfloat16 g_wqb[Dc*Dc];
__device__ __nv_bfloat16 g_wkb[Dc*Dc];
__device__ __nv_bfloat16 g_wvb[Dc*Dc];
__device__ __nv_bfloat16 g_wob[Dc*Dc];
__device__ __nv_bfloat16 g_wgqh[Dc*Dc];
__device__ __nv_bfloat16 g_wgqlo[Dc*Dc];
__device__ __nv_bfloat16 g_wroh[Dc*Dc];
__device__ __nv_bfloat16 g_wrolo[Dc*Dc];

// ---------------- helpers ----------------
__device__ __forceinline__ float warpSum(float v) {
    #pragma unroll
    for (int o = 16; o; o >>= 1) v += __shfl_xor_sync(0xffffffffu, v, o);
    return v;
}

#define CP16(dst, src) asm volatile("cp.async.cg.shared.global [%0], [%1], 16;\n" :: "r"(dst), "l"(src))
#define LDSM4(r0,r1,r2,r3,addr) \
    asm volatile("ldmatrix.sync.aligned.m8n8.x4.shared.b16 {%0,%1,%2,%3}, [%4];" \
                 : "=r"(r0),"=r"(r1),"=r"(r2),"=r"(r3) : "r"(addr))
#define MMA16816(d0,d1,d2,d3,a0,a1,a2,a3,b0,b1) \
    asm volatile("mma.sync.aligned.m16n8k16.row.col.f32.bf16.bf16.f32 " \
                 "{%0,%1,%2,%3}, {%4,%5,%6,%7}, {%8,%9}, {%0,%1,%2,%3};" \
                 : "+f"(d0),"+f"(d1),"+f"(d2),"+f"(d3) \
                 : "r"(a0),"r"(a1),"r"(a2),"r"(a3),"r"(b0),"r"(b1))

// ---------------- fp32 -> bf16 convert ----------------
__global__ __launch_bounds__(256) void cvt_bf16_kernel(
    const float* __restrict__ in, __nv_bfloat16* __restrict__ out)
{
    int i = blockIdx.x * 256 + threadIdx.x;
    float4 v = ((const float4*)in)[i];
    ((__nv_bfloat162*)out)[i*2]   = __floats2bfloat162_rn(v.x, v.y);
    ((__nv_bfloat162*)out)[i*2+1] = __floats2bfloat162_rn(v.z, v.w);
}

// ---------------- fp32 -> bf16 hi/lo split ----------------
__global__ __launch_bounds__(256) void split_cvt_kernel(
    const float* __restrict__ in, __nv_bfloat16* __restrict__ hi, __nv_bfloat16* __restrict__ lo)
{
    int i = blockIdx.x * 256 + threadIdx.x;
    float4 v = ((const float4*)in)[i];
    float h0 = __bfloat162float(__float2bfloat16(v.x));
    float h1 = __bfloat162float(__float2bfloat16(v.y));
    float h2 = __bfloat162float(__float2bfloat16(v.z));
    float h3 = __bfloat162float(__float2bfloat16(v.w));
    ((__nv_bfloat162*)hi)[i*2]   = __floats2bfloat162_rn(h0, h1);
    ((__nv_bfloat162*)hi)[i*2+1] = __floats2bfloat162_rn(h2, h3);
    ((__nv_bfloat162*)lo)[i*2]   = __floats2bfloat162_rn(v.x - h0, v.y - h1);
    ((__nv_bfloat162*)lo)[i*2+1] = __floats2bfloat162_rn(v.z - h2, v.w - h3);
}

// ---------------- RMSNorm (fp32 + bf16 hi/lo outputs) ----------------
__global__ __launch_bounds__(256) void rmsnorm_kernel(
    const float* __restrict__ x, const float* __restrict__ w,
    float* __restrict__ xn, __nv_bfloat16* __restrict__ xnb, __nv_bfloat16* __restrict__ xnlo)
{
    int n = blockIdx.x;
    const float* xp = x + (size_t)n * Dc;
    float s = 0.f;
    for (int d = threadIdx.x; d < Dc; d += 256) { float v = xp[d]; s += v * v; }
    __shared__ float red[8];
    s = warpSum(s);
    int warp = threadIdx.x >> 5, lane = threadIdx.x & 31;
    if (lane == 0) red[warp] = s;
    __syncthreads();
    if (warp == 0) {
        float t = lane < 8 ? red[lane] : 0.f;
        t = warpSum(t);
        if (lane == 0) red[0] = rsqrtf(t / (float)Dc + 1e-6f);
    }
    __syncthreads();
    float inv = red[0];
    float* op = xn + (size_t)n * Dc;
    __nv_bfloat16* ob = xnb + (size_t)n * Dc;
    __nv_bfloat16* ol = xnlo + (size_t)n * Dc;
    for (int d = threadIdx.x; d < Dc; d += 256) {
        float v = xp[d] * inv * w[d];
        __nv_bfloat16 hv = __float2bfloat16(v);
        op[d] = v;
        ob[d] = hv;
        ol[d] = __float2bfloat16(v - __bfloat162float(hv));
    }
}

// ---------------- bf16 tensor-core GEMM: C (+)= A @ W^T ----------------
#define TBM 128
#define TBN 128
#define TBK 64

__global__ __launch_bounds__(256, 2) void gemm_bf16(
    const __nv_bfloat16* __restrict__ A, const __nv_bfloat16* __restrict__ W,
    float* __restrict__ C, int M, int N, int Kd, int accum)
{
    extern __shared__ __nv_bfloat16 sm[];
    const int TILE = TBM * TBK;
    uint32_t sA = (uint32_t)__cvta_generic_to_shared(sm);
    uint32_t sB = sA + 2 * TILE * 2;

    int tid = threadIdx.x;
    int bm = blockIdx.y * TBM, bn = blockIdx.x * TBN;
    int warp = tid >> 5, lane = tid & 31;
    int wm = (warp >> 2) * 64;
    int wn = (warp & 3) * 32;

    int lrow = tid >> 1;
    int cbase = (tid & 1) * 4;
    int r7 = lrow & 7;
    const __nv_bfloat16* Ag = A + (size_t)(bm + lrow) * Kd;
    const __nv_bfloat16* Wg = W + (size_t)(bn + lrow) * Kd;
    uint32_t daBase = sA + (uint32_t)(lrow * TBK) * 2;
    uint32_t dbBase = sB + (uint32_t)(lrow * TBK) * 2;

    int arow = lane & 15;
    int ahk  = lane >> 4;
    int bnr  = (lane & 7) + ((lane >> 4) << 3);
    int bhk  = (lane >> 3) & 1;

    float acc[4][4][4] = {};
    const int NT = 1024 / TBK;

    {
        #pragma unroll
        for (int c = 0; c < 4; c++) {
            int ch = cbase + c;
            int pch = ch ^ r7;
            CP16(daBase + (uint32_t)pch * 16, Ag + ch * 8);
            CP16(dbBase + (uint32_t)pch * 16, Wg + ch * 8);
        }
        asm volatile("cp.async.commit_group;\n" ::);
    }

    int buf = 0;
    for (int t = 0; t < NT; t++) {
        if (t + 1 < NT) {
            int k0 = (t + 1) * TBK;
            uint32_t da = daBase + (uint32_t)((buf ^ 1) * TILE) * 2;
            uint32_t db = dbBase + (uint32_t)((buf ^ 1) * TILE) * 2;
            #pragma unroll
            for (int c = 0; c < 4; c++) {
                int ch = cbase + c;
                int pch = ch ^ r7;
                CP16(da + (uint32_t)pch * 16, Ag + k0 + ch * 8);
                CP16(db + (uint32_t)pch * 16, Wg + k0 + ch * 8);
            }
            asm volatile("cp.async.commit_group;\n" ::);
            asm volatile("cp.async.wait_group 1;\n" ::: "memory");
        } else {
            asm volatile("cp.async.wait_group 0;\n" ::: "memory");
        }
        __syncthreads();

        uint32_t aBuf = sA + (uint32_t)(buf * TILE) * 2;
        uint32_t bBuf = sB + (uint32_t)(buf * TILE) * 2;

        #pragma unroll
        for (int ks = 0; ks < 4; ks++) {
            uint32_t af[4][4];
            #pragma unroll
            for (int i = 0; i < 4; i++) {
                int row = wm + i * 16 + arow;
                int ch = ks * 2 + ahk;
                uint32_t addr = aBuf + (uint32_t)(row * TBK + ((ch ^ (row & 7)) << 3)) * 2;
                LDSM4(af[i][0], af[i][1], af[i][2], af[i][3], addr);
            }
            uint32_t bf[4][2];
            #pragma unroll
            for (int jp = 0; jp < 2; jp++) {
                int n = wn + jp * 16 + bnr;
                int ch = ks * 2 + bhk;
                uint32_t addr = bBuf + (uint32_t)(n * TBK + ((ch ^ (n & 7)) << 3)) * 2;
                LDSM4(bf[jp*2][0], bf[jp*2][1], bf[jp*2+1][0], bf[jp*2+1][1], addr);
            }
            #pragma unroll
            for (int i = 0; i < 4; i++)
                #pragma unroll
                for (int j = 0; j < 4; j++)
                    MMA16816(acc[i][j][0], acc[i][j][1], acc[i][j][2], acc[i][j][3],
                             af[i][0], af[i][1], af[i][2], af[i][3],
                             bf[j][0], bf[j][1]);
        }
        __syncthreads();
        buf ^= 1;
    }

    int g = lane >> 2, t2 = lane & 3;
    #pragma unroll
    for (int i = 0; i < 4; i++) {
        int row0 = bm + wm + i * 16 + g;
        #pragma unroll
        for (int j = 0; j < 4; j++) {
            int col = bn + wn + j * 8 + t2 * 2;
            float* p0 = C + (size_t)row0 * N + col;
            float* p1 = C + (size_t)(row0 + 8) * N + col;
            float2 v0 = make_float2(acc[i][j][0], acc[i][j][1]);
            float2 v1 = make_float2(acc[i][j][2], acc[i][j][3]);
            if (accum) {
                float2 c0 = *(float2*)p0, c1 = *(float2*)p1;
                v0.x += c0.x; v0.y += c0.y;
                v1.x += c1.x; v1.y += c1.y;
            }
            *(float2*)p0 = v0;
            *(float2*)p1 = v1;
        }
    }
}

// ---------------- RoPE (in-place on q and k), 8 warps/block ----------------
__global__ __launch_bounds__(256) void rope_kernel(float* __restrict__ q, float* __restrict__ k)
{
    int warp = threadIdx.x >> 5;
    int j = threadIdx.x & 31;
    int bth = blockIdx.x * 8 + warp;
    int t = (bth / Hc) % Tc;
    float inv = powf(10000.0f, -(float)j / 32.0f);
    float ang = (float)t * inv;
    float c, s;
    sincosf(ang, &s, &c);
    float* qp = q + (size_t)bth * Kc;
    float* kp = k + (size_t)bth * Kc;
    float q1 = qp[j], q2 = qp[j + 32];
    qp[j]      = q1 * c - q2 * s;
    qp[j + 32] = q2 * c + q1 * s;
    float k1 = kp[j], k2 = kp[j + 32];
    kp[j]      = k1 * c - k2 * s;
    kp[j + 32] = k2 * c + k1 * s;
}

// ---------------- Tiled sliding-window attention ----------------
// Block = (b,h, 64-query tile), 256 threads. 5 key chunks of 64, online softmax.
#define QT 64
__global__ __launch_bounds__(256) void attn_tiled(
    const float* __restrict__ q, const float* __restrict__ k,
    const float* __restrict__ v, __nv_bfloat16* __restrict__ out)
{
    extern __shared__ float smf[];
    float* Qs = smf;               // [64][64] d-major
    float* Ks = Qs + 4096;         // [64][64] d-major
    float* Vs = Ks + 4096;         // [64][64] row-major
    float* Ps = Vs + 4096;         // [64][68]

    int tid = threadIdx.x;
    int t0 = blockIdx.x * QT;
    int bh = blockIdx.y;
    int h = bh & (Hc - 1), b = bh >> 4;
    const size_t rowStride = (size_t)Hc * Kc;
    const float* qBase = q + ((size_t)(b * Tc + t0) * Hc + h) * Kc;

    {
        int qi = tid & 63, dq = (tid >> 6) * 16;
        const float4* src = (const float4*)(qBase + (size_t)qi * rowStride + dq);
        #pragma unroll
        for (int c = 0; c < 4; c++) {
            float4 val = src[c];
            int d = dq + c * 4;
            Qs[(d+0)*64+qi]=val.x; Qs[(d+1)*64+qi]=val.y; Qs[(d+2)*64+qi]=val.z; Qs[(d+3)*64+qi]=val.w;
        }
    }

    int qg = tid >> 4, kg = tid & 15;
    float m[4] = {-1e30f,-1e30f,-1e30f,-1e30f};
    float l[4] = {};
    float O[4][4] = {};

    #pragma unroll 1
    for (int c = 0; c < 5; c++) {
        int kt = t0 - (int)Wc + 64 * c;
        if (kt < 0) continue;

        __syncthreads();
        {
            int kk = tid & 63, dq = (tid >> 6) * 16;
            const float4* src = (const float4*)(k + ((size_t)(b * Tc + kt + kk) * Hc + h) * Kc + dq);
            #pragma unroll
            for (int cc = 0; cc < 4; cc++) {
                float4 val = src[cc];
                int d = dq + cc * 4;
                Ks[(d+0)*64+kk]=val.x; Ks[(d+1)*64+kk]=val.y; Ks[(d+2)*64+kk]=val.z; Ks[(d+3)*64+kk]=val.w;
            }
        }
        {
            #pragma unroll
            for (int cc = 0; cc < 4; cc++) {
                int i = tid + cc * 256;
                int row = i >> 4, col = (i & 15) * 4;
                *(float4*)&Vs[row * 64 + col] =
                    *(const float4*)(v + ((size_t)(b * Tc + kt + row) * Hc + h) * Kc + col);
            }
        }
        __syncthreads();

        float s[4][4] = {};
        #pragma unroll
        for (int d = 0; d < 64; d++) {
            float4 qv = *(const float4*)&Qs[d * 64 + 4 * qg];
            float4 kv = *(const float4*)&Ks[d * 64 + 4 * kg];
            float a[4] = {qv.x, qv.y, qv.z, qv.w};
            float bb[4] = {kv.x, kv.y, kv.z, kv.w};
            #pragma unroll
            for (int i = 0; i < 4; i++)
                #pragma unroll
                for (int j = 0; j < 4; j++)
                    s[i][j] = fmaf(a[i], bb[j], s[i][j]);
        }
        #pragma unroll
        for (int i = 0; i < 4; i++) {
            int t = t0 + 4 * qg + i;
            #pragma unroll
            for (int j = 0; j < 4; j++) {
                int st = kt + 4 * kg + j;
                int dt = t - st;
                s[i][j] = (dt < 0 || dt > (int)Wc) ? -1e30f : s[i][j] * 0.125f;
            }
        }
        float scale[4];
        #pragma unroll
        for (int i = 0; i < 4; i++) {
            float mx = fmaxf(fmaxf(s[i][0], s[i][1]), fmaxf(s[i][2], s[i][3]));
            #pragma unroll
            for (int o = 8; o; o >>= 1) mx = fmaxf(mx, __shfl_xor_sync(0xffffffffu, mx, o));
            float mn = fmaxf(m[i], mx);
            scale[i] = __expf(m[i] - mn);
            m[i] = mn;
            float sl = 0.f;
            #pragma unroll
            for (int j = 0; j < 4; j++) {
                float p = __expf(s[i][j] - mn);
                s[i][j] = p;
                sl += p;
            }
            #pragma unroll
            for (int o = 8; o; o >>= 1) sl += __shfl_xor_sync(0xffffffffu, sl, o);
            l[i] = l[i] * scale[i] + sl;
            #pragma unroll
            for (int j = 0; j < 4; j++) O[i][j] *= scale[i];
            *(float4*)&Ps[(4 * qg + i) * 68 + 4 * kg] = make_float4(s[i][0], s[i][1], s[i][2], s[i][3]);
        }
        __syncthreads();

        #pragma unroll 4
        for (int kk = 0; kk < 64; kk++) {
            float4 vv = *(const float4*)&Vs[kk * 64 + 4 * kg];
            float p0 = Ps[(4 * qg + 0) * 68 + kk];
            float p1 = Ps[(4 * qg + 1) * 68 + kk];
            float p2 = Ps[(4 * qg + 2) * 68 + kk];
            float p3 = Ps[(4 * qg + 3) * 68 + kk];
            O[0][0]=fmaf(p0,vv.x,O[0][0]); O[0][1]=fmaf(p0,vv.y,O[0][1]); O[0][2]=fmaf(p0,vv.z,O[0][2]); O[0][3]=fmaf(p0,vv.w,O[0][3]);
            O[1][0]=fmaf(p1,vv.x,O[1][0]); O[1][1]=fmaf(p1,vv.y,O[1][1]); O[1][2]=fmaf(p1,vv.z,O[1][2]); O[1][3]=fmaf(p1,vv.w,O[1][3]);
            O[2][0]=fmaf(p2,vv.x,O[2][0]); O[2][1]=fmaf(p2,vv.y,O[2][1]); O[2][2]=fmaf(p2,vv.z,O[2][2]); O[2][3]=fmaf(p2,vv.w,O[2][3]);
            O[3][0]=fmaf(p3,vv.x,O[3][0]); O[3][1]=fmaf(p3,vv.y,O[3][1]); O[3][2]=fmaf(p3,vv.z,O[3][2]); O[3][3]=fmaf(p3,vv.w,O[3][3]);
        }
    }

    #pragma unroll
    for (int i = 0; i < 4; i++) {
        float inv = 1.0f / l[i];
        int t = t0 + 4 * qg + i;
        __nv_bfloat162* op = (__nv_bfloat162*)(out + ((size_t)(b * Tc + t) * Hc + h) * Vc + 4 * kg);
        op[0] = __floats2bfloat162_rn(O[i][0] * inv, O[i][1] * inv);
        op[1] = __floats2bfloat162_rn(O[i][2] * inv, O[i][3] * inv);
    }
}

// ---------------- gather-replace q_g from key_bank ----------------
__global__ __launch_bounds__(256) void gather_kernel(
    const int* __restrict__ input_ids, const float* __restrict__ key_bank,
    float* __restrict__ qg)
{
    int n = blockIdx.x;
    int idx = input_ids[n] - CUEc;
    if (idx < 0 || idx >= BANKc) return;
    for (int i = threadIdx.x; i < Hc * Kc; i += 256) {
        int h = i >> 6, kk = i & 63;
        qg[(size_t)n * (Hc * Kc) + i] = key_bank[((size_t)h * BANKc + idx) * Kc + kk];
    }
}

// ---------------- retrieval einsum (outputs bf16 hi/lo) ----------------
__global__ __launch_bounds__(256) void retrieve_kernel(
    const float* __restrict__ state, const float* __restrict__ qg,
    __nv_bfloat16* __restrict__ outh, __nv_bfloat16* __restrict__ outlo)
{
    __shared__ float st[Kc * Vc];
    __shared__ float qsh[8][Kc];
    int bh = blockIdx.x;
    int b = bh / Hc, h = bh % Hc;
    const float* sp = state + (size_t)bh * Kc * Vc;
    for (int i = threadIdx.x; i < Kc * Vc; i += 256) st[i] = sp[i];
    int warp = threadIdx.x >> 5, lane = threadIdx.x & 31;
    int t = blockIdx.y * 8 + warp;
    const float* qp = qg + ((size_t)(b * Tc + t) * Hc + h) * Kc;
    qsh[warp][lane]      = qp[lane];
    qsh[warp][lane + 32] = qp[lane + 32];
    __syncthreads();
    float o0 = 0.f, o1 = 0.f;
    #pragma unroll
    for (int kk = 0; kk < Kc; kk++) {
        float qv = qsh[warp][kk];
        float2 s2 = ((const float2*)(st + kk * Vc))[lane];
        o0 = fmaf(qv, s2.x, o0);
        o1 = fmaf(qv, s2.y, o1);
    }
    size_t off = ((size_t)(b * Tc + t) * Hc + h) * Vc;
    float h0 = __bfloat162float(__float2bfloat16(o0));
    float h1 = __bfloat162float(__float2bfloat16(o1));
    ((__nv_bfloat162*)(outh  + off))[lane] = __floats2bfloat162_rn(h0, h1);
    ((__nv_bfloat162*)(outlo + off))[lane] = __floats2bfloat162_rn(o0 - h0, o1 - h1);
}

// ---------------- gate mean ----------------
__global__ __launch_bounds__(512) void gate_kernel(
    const float* __restrict__ xn, const float* __restrict__ w_gate,
    const float* __restrict__ b_gate, float* __restrict__ gmean)
{
    __shared__ float gsh[Hc];
    int n = blockIdx.x;
    int warp = threadIdx.x >> 5, lane = threadIdx.x & 31;
    const float* xp = xn + (size_t)n * Dc;
    const float* wp = w_gate + (size_t)warp * Dc;
    float s = 0.f;
    for (int d = lane; d < Dc; d += 32) s = fmaf(xp[d], wp[d], s);
    s = warpSum(s);
    if (lane == 0) gsh[warp] = 1.0f / (1.0f + __expf(-(s + b_gate[warp])));
    __syncthreads();
    if (threadIdx.x == 0) {
        float acc = 0.f;
        #pragma unroll
        for (int h = 0; h < Hc; h++) acc += gsh[h];
        gmean[n] = acc / (float)Hc;
    }
}

// ---------------- final combine ----------------
__global__ __launch_bounds__(256) void combine_kernel(
    const float* __restrict__ x, const float* __restrict__ localp,
    const float* __restrict__ retout, const float* __restrict__ gmean,
    float* __restrict__ out)
{
    int i = blockIdx.x * 256 + threadIdx.x;
    int n = i >> 10;
    out[i] = x[i] + 0.3f * localp[i] + gmean[n] * retout[i];
}

// ---------------- launch ----------------
extern "C" void kernel_launch(void* const* d_in, const int* in_sizes, int n_in,
                              void* d_out, int out_size)
{
    const float* x         = (const float*)d_in[0];
    const float* gdn_state = (const float*)d_in[1];
    const int*   input_ids = (const int*)  d_in[2];
    const float* key_bank  = (const float*)d_in[3];
    const float* norm_w    = (const float*)d_in[4];
    const float* wq        = (const float*)d_in[5];
    const float* wk        = (const float*)d_in[6];
    const float* wv        = (const float*)d_in[7];
    const float* wo        = (const float*)d_in[8];
    const float* w_gq      = (const float*)d_in[9];
    const float* w_ro      = (const float*)d_in[10];
    const float* w_gate    = (const float*)d_in[11];
    const float* b_gate    = (const float*)d_in[12];
    float* out = (float*)d_out;

    float *xn, *q, *k, *v, *localp, *qg, *retout, *gmean;
    __nv_bfloat16 *xnb, *xnlo, *attnb, *retrh, *retrlo;
    __nv_bfloat16 *wqb, *wkb, *wvb, *wob, *wgqh, *wgqlo, *wroh, *wrolo;
    cudaGetSymbolAddress((void**)&xn,     g_xn);
    cudaGetSymbolAddress((void**)&q,      g_q);
    cudaGetSymbolAddress((void**)&k,      g_k);
    cudaGetSymbolAddress((void**)&v,      g_v);
    cudaGetSymbolAddress((void**)&localp, g_localp);
    cudaGetSymbolAddress((void**)&qg,     g_qg);
    cudaGetSymbolAddress((void**)&retout, g_retout);
    cudaGetSymbolAddress((void**)&gmean,  g_gmean);
    cudaGetSymbolAddress((void**)&xnb,    g_xnb);
    cudaGetSymbolAddress((void**)&xnlo,   g_xnlo);
    cudaGetSymbolAddress((void**)&attnb,  g_attnb);
    cudaGetSymbolAddress((void**)&retrh,  g_retrh);
    cudaGetSymbolAddress((void**)&retrlo, g_retrlo);
    cudaGetSymbolAddress((void**)&wqb,    g_wqb);
    cudaGetSymbolAddress((void**)&wkb,    g_wkb);
    cudaGetSymbolAddress((void**)&wvb,    g_wvb);
    cudaGetSymbolAddress((void**)&wob,    g_wob);
    cudaGetSymbolAddress((void**)&wgqh,   g_wgqh);
    cudaGetSymbolAddress((void**)&wgqlo,  g_wgqlo);
    cudaGetSymbolAddress((void**)&wroh,   g_wroh);
    cudaGetSymbolAddress((void**)&wrolo,  g_wrolo);

    cudaFuncSetAttribute(gemm_bf16, cudaFuncAttributeMaxDynamicSharedMemorySize, 65536);
    cudaFuncSetAttribute(attn_tiled, cudaFuncAttributeMaxDynamicSharedMemorySize, 68608);

    // 0. weight conversions
    {
        int blocks = (Dc * Dc) / (256 * 4);
        cvt_bf16_kernel<<<blocks, 256>>>(wq, wqb);
        cvt_bf16_kernel<<<blocks, 256>>>(wk, wkb);
        cvt_bf16_kernel<<<blocks, 256>>>(wv, wvb);
        cvt_bf16_kernel<<<blocks, 256>>>(wo, wob);
        split_cvt_kernel<<<blocks, 256>>>(w_gq, wgqh, wgqlo);
        split_cvt_kernel<<<blocks, 256>>>(w_ro, wroh, wrolo);
    }

    // 1. RMSNorm (fp32 + bf16 hi/lo)
    rmsnorm_kernel<<<NTOK, 256>>>(x, norm_w, xn, xnb, xnlo);

    dim3 tgrid(Dc / TBN, NTOK / TBM);
    // 2. projections (bf16 tensor core)
    gemm_bf16<<<tgrid, 256, 65536>>>(xnb, wqb, q, NTOK, Dc, Dc, 0);
    gemm_bf16<<<tgrid, 256, 65536>>>(xnb, wkb, k, NTOK, Dc, Dc, 0);
    gemm_bf16<<<tgrid, 256, 65536>>>(xnb, wvb, v, NTOK, Dc, Dc, 0);

    // q_g projection: split-bf16 (hi*hi + hi*lo + lo*hi)
    gemm_bf16<<<tgrid, 256, 65536>>>(xnb,  wgqh,  qg, NTOK, Dc, Dc, 0);
    gemm_bf16<<<tgrid, 256, 65536>>>(xnb,  wgqlo, qg, NTOK, Dc, Dc, 1);
    gemm_bf16<<<tgrid, 256, 65536>>>(xnlo, wgqh,  qg, NTOK, Dc, Dc, 1);

    // 3. RoPE
    rope_kernel<<<Bc * Tc * Hc / 8, 256>>>(q, k);

    // 4. tiled attention (writes bf16)
    {
        dim3 ag(Tc / QT, Bc * Hc);
        attn_tiled<<<ag, 256, 68608>>>(q, k, v, attnb);
    }

    // 5. local output projection (bf16 tensor core)
    gemm_bf16<<<tgrid, 256, 65536>>>(attnb, wob, localp, NTOK, Dc, Dc, 0);

    // 6. gather-replace q_g
    gather_kernel<<<NTOK, 256>>>(input_ids, key_bank, qg);

    // 7. retrieval einsum (writes bf16 hi/lo)
    {
        dim3 rg(Bc * Hc, Tc / 8);
        retrieve_kernel<<<rg, 256>>>(gdn_state, qg, retrh, retrlo);
    }

    // 8. retrieval output projection: split-bf16
    gemm_bf16<<<tgrid, 256, 65536>>>(retrh,  wroh,  retout, NTOK, Dc, Dc, 0);
    gemm_bf16<<<tgrid, 256, 65536>>>(retrh,  wrolo, retout, NTOK, Dc, Dc, 1);
    gemm_bf16<<<tgrid, 256, 65536>>>(retrlo, wroh,  retout, NTOK, Dc, Dc, 1);

    // 9. gate
    gate_kernel<<<NTOK, 512>>>(xn, w_gate, b_gate, gmean);

    // 10. combine
    combine_kernel<<<NELEM / 256, 256>>>(x, localp, retout, gmean, out);
}